// round 6
// baseline (speedup 1.0000x reference)
#include <cuda_runtime.h>
#include <cuda_fp16.h>
#include <stdint.h>

#define N_NODES 100000
#define BATCH   50000
#define K       10
#define DIM     128

// fp16 feature table: 25.6 MB. Together with the fp32 features (51.2 MB,
// read-only, replay-resident) and indices this fits in the 126 MB L2.
__device__ __half g_tab16[N_NODES * DIM];

// ---------------------------------------------------------------------------
// Pass 1: fp32 -> fp16 table. DEFAULT cache policy on the feature reads:
// they are re-read every graph replay and must stay L2-resident.
// ---------------------------------------------------------------------------
__global__ __launch_bounds__(256) void convert_kernel(const float4* __restrict__ feat)
{
    const int i = blockIdx.x * blockDim.x + threadIdx.x;   // one uint4 (8 halfs)
    const int n8 = N_NODES * DIM / 8;                      // 1.6M
    if (i >= n8) return;

    float4 a = __ldg(&feat[i * 2 + 0]);
    float4 b = __ldg(&feat[i * 2 + 1]);

    __half2 h0 = __float22half2_rn(make_float2(a.x, a.y));
    __half2 h1 = __float22half2_rn(make_float2(a.z, a.w));
    __half2 h2 = __float22half2_rn(make_float2(b.x, b.y));
    __half2 h3 = __float22half2_rn(make_float2(b.z, b.w));

    uint4 packed;
    packed.x = *reinterpret_cast<unsigned*>(&h0);
    packed.y = *reinterpret_cast<unsigned*>(&h1);
    packed.z = *reinterpret_cast<unsigned*>(&h2);
    packed.w = *reinterpret_cast<unsigned*>(&h3);
    reinterpret_cast<uint4*>(g_tab16)[i] = packed;
}

// ---------------------------------------------------------------------------
// Pass 2: gather-mean. HALF-WARP per output row: fp16 row = 256B = 16 lanes
// x uint4 (16B). Each warp produces 2 rows with 11 LDG.128 (MLP=11 x 16B per
// lane). Inner loop: 4 HADD2 per k. Output streamed with __stcs.
// ---------------------------------------------------------------------------
__global__ __launch_bounds__(256) void gather_kernel(
    const int* __restrict__ nodes,
    const int* __restrict__ neighbours,
    float4* __restrict__ out)
{
    const int gwarp = (blockIdx.x * blockDim.x + threadIdx.x) >> 5;
    const int lane  = threadIdx.x & 31;
    const int half  = lane >> 4;          // which of the 2 rows this lane serves
    const int hl    = lane & 15;          // lane within the half-warp
    const int row   = gwarp * 2 + half;
    if (row >= BATCH) return;

    int idx[K + 1];
    idx[0] = nodes[row];
#pragma unroll
    for (int k = 0; k < K; k++) idx[k + 1] = neighbours[row * K + k];

    // table as uint4: row stride = 256B / 16B = 16
    const uint4* __restrict__ tab = reinterpret_cast<const uint4*>(g_tab16);

    // Front-batch all 11 gathered 16B loads.
    uint4 v[K + 1];
#pragma unroll
    for (int k = 0; k < K + 1; k++) {
        v[k] = __ldg(&tab[idx[k] * 16 + hl]);
    }

    __half2 a0 = *reinterpret_cast<__half2*>(&v[0].x);
    __half2 a1 = *reinterpret_cast<__half2*>(&v[0].y);
    __half2 a2 = *reinterpret_cast<__half2*>(&v[0].z);
    __half2 a3 = *reinterpret_cast<__half2*>(&v[0].w);
#pragma unroll
    for (int k = 1; k < K + 1; k++) {
        a0 = __hadd2(a0, *reinterpret_cast<__half2*>(&v[k].x));
        a1 = __hadd2(a1, *reinterpret_cast<__half2*>(&v[k].y));
        a2 = __hadd2(a2, *reinterpret_cast<__half2*>(&v[k].z));
        a3 = __hadd2(a3, *reinterpret_cast<__half2*>(&v[k].w));
    }

    const float s = 1.0f / (float)(K + 1);
    float2 f0 = __half22float2(a0);
    float2 f1 = __half22float2(a1);
    float2 f2 = __half22float2(a2);
    float2 f3 = __half22float2(a3);

    float4 o0 = make_float4(f0.x * s, f0.y * s, f1.x * s, f1.y * s);
    float4 o1 = make_float4(f2.x * s, f2.y * s, f3.x * s, f3.y * s);

    // fp32 output row = 32 float4; this lane owns float4 slots 2*hl, 2*hl+1.
    __stcs(&out[row * 32 + hl * 2 + 0], o0);
    __stcs(&out[row * 32 + hl * 2 + 1], o1);
}

extern "C" void kernel_launch(void* const* d_in, const int* in_sizes, int n_in,
                              void* d_out, int out_size)
{
    const int*    nodes      = (const int*)d_in[0];
    const int*    neighbours = (const int*)d_in[1];
    const float4* features   = (const float4*)d_in[2];
    float4*       out        = (float4*)d_out;

    const int n8 = N_NODES * DIM / 8;
    convert_kernel<<<(n8 + 255) / 256, 256>>>(features);

    // 2 rows per warp -> 25000 warps -> 3125 blocks of 256 threads.
    const int warps_needed = (BATCH + 1) / 2;
    const int blocks = (warps_needed + 7) / 8;
    gather_kernel<<<blocks, 256>>>(nodes, neighbours, out);
}

// round 7
// speedup vs baseline: 1.1792x; 1.1792x over previous
#include <cuda_runtime.h>

#define BATCH 50000
#define K 10
#define DIM 128
#define VECS_PER_ROW (DIM / 4)   // 32 float4 per row — one per lane

// One warp per output row; lane owns one float4 (32 x 16B = 512B row).
// __launch_bounds__(128, 6): 85-register budget so ALL 11 staged float4
// (44 regs) + addresses live in registers -> true MLP=11 in SASS, instead of
// the reg-budget-serialized loads the 32-reg default produced in round 1.
__global__ __launch_bounds__(128, 6) void mean_agg_kernel(
    const int* __restrict__ nodes,        // [BATCH]
    const int* __restrict__ neighbours,   // [BATCH, K]
    const float4* __restrict__ features,  // [N_NODES, 32] as float4
    float4* __restrict__ out)             // [BATCH, 32] as float4
{
    const int warp = (blockIdx.x * blockDim.x + threadIdx.x) >> 5;
    const int lane = threadIdx.x & 31;
    if (warp >= BATCH) return;

    int idx[K + 1];
    idx[0] = nodes[warp];
#pragma unroll
    for (int k = 0; k < K; k++) idx[k + 1] = neighbours[warp * K + k];

    // All 11 gathered float4 loads issued before any consumption.
    float4 v[K + 1];
#pragma unroll
    for (int k = 0; k < K + 1; k++) {
        v[k] = __ldg(&features[(long long)idx[k] * VECS_PER_ROW + lane]);
    }

    // Pairwise tree: shorter dependency chain than a serial fold, so the
    // first adds only need the first loads, not all of them.
    float4 s0, s1, s2, s3, s4;
    s0.x = v[0].x + v[1].x;  s0.y = v[0].y + v[1].y;  s0.z = v[0].z + v[1].z;  s0.w = v[0].w + v[1].w;
    s1.x = v[2].x + v[3].x;  s1.y = v[2].y + v[3].y;  s1.z = v[2].z + v[3].z;  s1.w = v[2].w + v[3].w;
    s2.x = v[4].x + v[5].x;  s2.y = v[4].y + v[5].y;  s2.z = v[4].z + v[5].z;  s2.w = v[4].w + v[5].w;
    s3.x = v[6].x + v[7].x;  s3.y = v[6].y + v[7].y;  s3.z = v[6].z + v[7].z;  s3.w = v[6].w + v[7].w;
    s4.x = v[8].x + v[9].x;  s4.y = v[8].y + v[9].y;  s4.z = v[8].z + v[9].z;  s4.w = v[8].w + v[9].w;

    float4 t0, t1;
    t0.x = s0.x + s1.x;  t0.y = s0.y + s1.y;  t0.z = s0.z + s1.z;  t0.w = s0.w + s1.w;
    t1.x = s2.x + s3.x;  t1.y = s2.y + s3.y;  t1.z = s2.z + s3.z;  t1.w = s2.w + s3.w;

    float4 acc;
    acc.x = (t0.x + t1.x) + (s4.x + v[10].x);
    acc.y = (t0.y + t1.y) + (s4.y + v[10].y);
    acc.z = (t0.z + t1.z) + (s4.z + v[10].z);
    acc.w = (t0.w + t1.w) + (s4.w + v[10].w);

    const float s = 1.0f / (float)(K + 1);
    acc.x *= s; acc.y *= s; acc.z *= s; acc.w *= s;

    // Streaming store: output is write-once, keep it out of L2's way.
    __stcs(&out[(long long)warp * VECS_PER_ROW + lane], acc);
}

extern "C" void kernel_launch(void* const* d_in, const int* in_sizes, int n_in,
                              void* d_out, int out_size)
{
    const int*    nodes      = (const int*)d_in[0];
    const int*    neighbours = (const int*)d_in[1];
    const float4* features   = (const float4*)d_in[2];
    float4*       out        = (float4*)d_out;

    // One warp per row, 4 warps per 128-thread block.
    const int warps_per_block = 128 / 32;
    const int blocks = (BATCH + warps_per_block - 1) / warps_per_block;
    mean_agg_kernel<<<blocks, 128>>>(nodes, neighbours, features, out);
}